// round 16
// baseline (speedup 1.0000x reference)
#include <cuda_runtime.h>
#include <cstdint>

#define BSZ 4
#define LQ  512
#define LK  2048
#define DM  1024
#define NH  16
#define DK  64
#define VOCAB_B 900

// ---------------- scratch (static device memory; no runtime alloc) ----------
__device__ float g_Qp[BSZ * LQ * DM];
__device__ float g_Kp[BSZ * LK * DM];
__device__ float g_Vt[BSZ * DM * LK];                  // V projected+transposed
__device__ float g_Ao[BSZ * LQ * DM];
__device__ float g_Wr[4 * DM * DM];                    // tf32-rounded weights
__device__ unsigned short g_bm[BSZ * LQ * LK];         // packed b_idx|mask<<15

// ---------------- PTX helpers ----------------------------------------------
__device__ __forceinline__ uint32_t s_u32(const void* p) {
    uint32_t a;
    asm("{.reg .u64 t; cvta.to.shared.u64 t, %1; cvt.u32.u64 %0, t;}"
        : "=r"(a) : "l"(p));
    return a;
}

__device__ __forceinline__ float rtf32(float x) {
    uint32_t u = __float_as_uint(x);
    asm("cvt.rna.tf32.f32 %0,%0;" : "+r"(u));
    return __uint_as_float(u);
}

#define LDSM4(R0,R1,R2,R3,ADDR) \
    asm volatile("ldmatrix.sync.aligned.m8n8.x4.shared.b16 {%0,%1,%2,%3},[%4];" \
        : "=r"(R0),"=r"(R1),"=r"(R2),"=r"(R3) : "r"(ADDR))

#define CVT_TF32(T) asm volatile("cvt.rna.tf32.f32 %0,%0;" : "+r"(T))

#define MMA_TF32(D,A,B0,B1) \
    asm volatile("mma.sync.aligned.m16n8k8.row.col.f32.tf32.tf32.f32 " \
        "{%0,%1,%2,%3},{%4,%5,%6,%7},{%8,%9},{%0,%1,%2,%3};" \
        : "+f"(D[0]),"+f"(D[1]),"+f"(D[2]),"+f"(D[3]) \
        : "r"(A[0]),"r"(A[1]),"r"(A[2]),"r"(A[3]),"r"(B0),"r"(B1))

#define CP16(DST,SRC) \
    asm volatile("cp.async.cg.shared.global [%0],[%1],16;" :: "r"(DST),"l"(SRC))
#define CPCOMMIT  asm volatile("cp.async.commit_group;")
#define CPWAIT0   asm volatile("cp.async.wait_group 0;")
#define CPWAIT1   asm volatile("cp.async.wait_group 1;")

// ============================================================================
// round all 4 weight matrices in ONE launch
// ============================================================================
__global__ __launch_bounds__(256) void round_w4_kernel(
    const float4* __restrict__ w0, const float4* __restrict__ w1,
    const float4* __restrict__ w2, const float4* __restrict__ w3,
    float4* __restrict__ out, int n4)
{
    const float4* src = (blockIdx.y == 0) ? w0 : (blockIdx.y == 1) ? w1 :
                        (blockIdx.y == 2) ? w2 : w3;
    float4* dst = out + (size_t)blockIdx.y * n4;
    const int s = gridDim.x * 256;
    for (int i = blockIdx.x * 256 + threadIdx.x; i < n4; i += s) {
        float4 v = src[i];
        v.x = rtf32(v.x); v.y = rtf32(v.y);
        v.z = rtf32(v.z); v.w = rtf32(v.w);
        dst[i] = v;
    }
}

// ============================================================================
// pack b_idx + mask -> uint16 (idx | mask<<15), 4x ILP grid-strided
// ============================================================================
__device__ __forceinline__ ushort4 pack4(int4 ix, int4 mk) {
    ushort4 o;
    o.x = (unsigned short)(ix.x | (mk.x << 15));
    o.y = (unsigned short)(ix.y | (mk.y << 15));
    o.z = (unsigned short)(ix.z | (mk.z << 15));
    o.w = (unsigned short)(ix.w | (mk.w << 15));
    return o;
}
__global__ __launch_bounds__(256) void pack_bm_kernel(
    const int4* __restrict__ b_idx, const int4* __restrict__ mask,
    ushort4* __restrict__ bm, int n4)
{
    const int s = gridDim.x * 256;
    int i = blockIdx.x * 256 + threadIdx.x;
    if (i + 3 * s < n4) {
        int4 a0 = b_idx[i],         a1 = b_idx[i + s],
             a2 = b_idx[i + 2 * s], a3 = b_idx[i + 3 * s];
        int4 m0 = mask[i],          m1 = mask[i + s],
             m2 = mask[i + 2 * s],  m3 = mask[i + 3 * s];
        bm[i]         = pack4(a0, m0);
        bm[i + s]     = pack4(a1, m1);
        bm[i + 2 * s] = pack4(a2, m2);
        bm[i + 3 * s] = pack4(a3, m3);
    } else {
        for (; i < n4; i += s) bm[i] = pack4(b_idx[i], mask[i]);
    }
}

// ============================================================================
// FUSED Q/K/V projection (unchanged, round-15 proven)
// ============================================================================
__global__ __launch_bounds__(128, 2) void proj_qkv_tf32(
    const float* __restrict__ q, const float* __restrict__ k,
    const float* __restrict__ v, const float* __restrict__ Wr,
    const float* __restrict__ bq, const float* __restrict__ bk,
    const float* __restrict__ bv,
    float* __restrict__ Qp, float* __restrict__ Kp, float* __restrict__ Vt)
{
    extern __shared__ float smem[];
    const uint32_t sbase = s_u32(smem);
    const int tid = threadIdx.x;
    const int y = blockIdx.y;

    const float* A;  const float* B;  const float* bias;  float* C;
    int m0;  bool transv;
    if (y < 16)      { A = q; B = Wr;              bias = bq; C = Qp; m0 = y * 128;        transv = false; }
    else if (y < 80) { A = k; B = Wr + DM * DM;    bias = bk; C = Kp; m0 = (y - 16) * 128; transv = false; }
    else             { A = v; B = Wr + 2 * DM * DM; bias = bv; C = Vt; m0 = (y - 80) * 128; transv = true; }

    const int n0 = blockIdx.x * 128;
    const int l  = tid & 31, w = tid >> 5;
    const int mw = (w >> 1) * 64, nw = (w & 1) * 64;
    const int lrow = l & 15, lq_ = l >> 4, lx = l & 7;

    float acc[4][8][4];
#pragma unroll
    for (int i = 0; i < 4; i++)
#pragma unroll
        for (int j = 0; j < 8; j++)
#pragma unroll
            for (int r = 0; r < 4; r++) acc[i][j][r] = 0.f;

#define STAGE_P(IT, BUF) do {                                                  \
    uint32_t sA_ = sbase + (BUF) * 32768;                                      \
    uint32_t sB_ = sA_ + 16384;                                                \
    const float* Ag_ = A + (size_t)(m0) * DM + (IT) * 32;                      \
    const float* Bg_ = B + (size_t)(n0) * DM + (IT) * 32;                      \
    _Pragma("unroll")                                                          \
    for (int i_ = 0; i_ < 8; i_++) {                                           \
        int gi_ = tid + i_ * 128;                                              \
        int r_ = gi_ >> 3, g_ = gi_ & 7;                                       \
        CP16(sA_ + r_ * 128 + (((g_ ^ (r_ & 7)) << 4)),                        \
             Ag_ + (size_t)r_ * DM + g_ * 4);                                  \
    }                                                                          \
    _Pragma("unroll")                                                          \
    for (int i_ = 0; i_ < 8; i_++) {                                           \
        int gi_ = tid + i_ * 128;                                              \
        int r_ = gi_ >> 3, g_ = gi_ & 7;                                       \
        CP16(sB_ + r_ * 128 + (((g_ ^ (r_ & 7)) << 4)),                        \
             Bg_ + (size_t)r_ * DM + g_ * 4);                                  \
    }                                                                          \
} while (0)

    STAGE_P(0, 0);
    CPCOMMIT;

    int buf = 0;
    for (int it = 0; it < DM / 32; ++it) {
        if (it + 1 < DM / 32) { STAGE_P(it + 1, buf ^ 1); CPCOMMIT; CPWAIT1; }
        else                  { CPWAIT0; }
        __syncthreads();

        const uint32_t sA = sbase + buf * 32768;
        const uint32_t sB = sA + 16384;
        const uint32_t aAdr0 = sA + (mw + lrow) * 128;
        const uint32_t bAdr0 = sB + (nw + (l & 7)) * 128;

#pragma unroll
        for (int s = 0; s < 4; s += 2) {
            uint32_t bfr[8][4];
#pragma unroll
            for (int nf = 0; nf < 8; nf++) {
                uint32_t ad = bAdr0 + nf * 1024 +
                              (((2 * s + ((l >> 3) & 3)) ^ lx) << 4);
                LDSM4(bfr[nf][0], bfr[nf][1], bfr[nf][2], bfr[nf][3], ad);
            }
#pragma unroll
            for (int ss = 0; ss < 2; ss++) {
                uint32_t a[4][4];
#pragma unroll
                for (int mf = 0; mf < 4; mf++) {
                    uint32_t ad = aAdr0 + mf * 2048 +
                                  (((2 * (s + ss) + lq_) ^ lx) << 4);
                    LDSM4(a[mf][0], a[mf][1], a[mf][2], a[mf][3], ad);
                    CVT_TF32(a[mf][0]); CVT_TF32(a[mf][1]);
                    CVT_TF32(a[mf][2]); CVT_TF32(a[mf][3]);
                }
#pragma unroll
                for (int mf = 0; mf < 4; mf++)
#pragma unroll
                    for (int nf = 0; nf < 8; nf++)
                        MMA_TF32(acc[mf][nf], a[mf], bfr[nf][2 * ss], bfr[nf][2 * ss + 1]);
            }
        }
        __syncthreads();
        buf ^= 1;
    }
#undef STAGE_P

    if (transv) {
        __syncthreads();
#pragma unroll
        for (int mf = 0; mf < 4; mf++) {
            int mloc = mw + mf * 16 + (l >> 2);
#pragma unroll
            for (int nf = 0; nf < 8; nf++) {
                int nloc = nw + nf * 8 + (l & 3) * 2;
                float2 bb = *(const float2*)&bias[n0 + nloc];
                smem[(nloc)     * 132 + mloc]     = rtf32(acc[mf][nf][0] + bb.x);
                smem[(nloc + 1) * 132 + mloc]     = rtf32(acc[mf][nf][1] + bb.y);
                smem[(nloc)     * 132 + mloc + 8] = rtf32(acc[mf][nf][2] + bb.x);
                smem[(nloc + 1) * 132 + mloc + 8] = rtf32(acc[mf][nf][3] + bb.y);
            }
        }
        __syncthreads();
        const int bb_ = m0 / LK;
        const int kb_ = m0 % LK;
#pragma unroll
        for (int i = 0; i < 32; i++) {
            int n = w * 32 + i;
            float4 vv = *(const float4*)&smem[n * 132 + 4 * l];
            *(float4*)&C[((size_t)(bb_ * DM + n0 + n)) * LK + kb_ + 4 * l] = vv;
        }
    } else {
#pragma unroll
        for (int mf = 0; mf < 4; mf++) {
            int row = m0 + mw + mf * 16 + (l >> 2);
#pragma unroll
            for (int nf = 0; nf < 8; nf++) {
                int col = n0 + nw + nf * 8 + (l & 3) * 2;
                float2 bb = *(const float2*)&bias[col];
                float2 o0, o1;
                o0.x = rtf32(acc[mf][nf][0] + bb.x);
                o0.y = rtf32(acc[mf][nf][1] + bb.y);
                o1.x = rtf32(acc[mf][nf][2] + bb.x);
                o1.y = rtf32(acc[mf][nf][3] + bb.y);
                *(float2*)&C[(size_t)row * DM + col]       = o0;
                *(float2*)&C[(size_t)(row + 8) * DM + col] = o1;
            }
        }
    }
}

// ============================================================================
// Output projection (unchanged, round-15 proven)
// ============================================================================
__global__ __launch_bounds__(128, 2) void gemm_out_tf32(
    const float* __restrict__ A, const float* __restrict__ B,
    const float* __restrict__ bias, float* __restrict__ C)
{
    extern __shared__ float smem[];
    const uint32_t sbase = s_u32(smem);
    const int tid = threadIdx.x;
    const int m0 = blockIdx.y * 128, n0 = blockIdx.x * 128;
    const int l  = tid & 31, w = tid >> 5;
    const int mw = (w >> 1) * 64, nw = (w & 1) * 64;
    const int lrow = l & 15, lq_ = l >> 4, lx = l & 7;

    float acc[4][8][4];
#pragma unroll
    for (int i = 0; i < 4; i++)
#pragma unroll
        for (int j = 0; j < 8; j++)
#pragma unroll
            for (int r = 0; r < 4; r++) acc[i][j][r] = 0.f;

#define STAGE_O(IT, BUF) do {                                                  \
    uint32_t sA_ = sbase + (BUF) * 32768;                                      \
    uint32_t sB_ = sA_ + 16384;                                                \
    const float* Ag_ = A + (size_t)(m0) * DM + (IT) * 32;                      \
    const float* Bg_ = B + (size_t)(n0) * DM + (IT) * 32;                      \
    _Pragma("unroll")                                                          \
    for (int i_ = 0; i_ < 8; i_++) {                                           \
        int gi_ = tid + i_ * 128;                                              \
        int r_ = gi_ >> 3, g_ = gi_ & 7;                                       \
        CP16(sA_ + r_ * 128 + (((g_ ^ (r_ & 7)) << 4)),                        \
             Ag_ + (size_t)r_ * DM + g_ * 4);                                  \
    }                                                                          \
    _Pragma("unroll")                                                          \
    for (int i_ = 0; i_ < 8; i_++) {                                           \
        int gi_ = tid + i_ * 128;                                              \
        int r_ = gi_ >> 3, g_ = gi_ & 7;                                       \
        CP16(sB_ + r_ * 128 + (((g_ ^ (r_ & 7)) << 4)),                        \
             Bg_ + (size_t)r_ * DM + g_ * 4);                                  \
    }                                                                          \
} while (0)

    STAGE_O(0, 0);
    CPCOMMIT;

    int buf = 0;
    for (int it = 0; it < DM / 32; ++it) {
        if (it + 1 < DM / 32) { STAGE_O(it + 1, buf ^ 1); CPCOMMIT; CPWAIT1; }
        else                  { CPWAIT0; }
        __syncthreads();

        const uint32_t sA = sbase + buf * 32768;
        const uint32_t sB = sA + 16384;
        const uint32_t aAdr0 = sA + (mw + lrow) * 128;
        const uint32_t bAdr0 = sB + (nw + (l & 7)) * 128;

#pragma unroll
        for (int s = 0; s < 4; s += 2) {
            uint32_t bfr[8][4];
#pragma unroll
            for (int nf = 0; nf < 8; nf++) {
                uint32_t ad = bAdr0 + nf * 1024 +
                              (((2 * s + ((l >> 3) & 3)) ^ lx) << 4);
                LDSM4(bfr[nf][0], bfr[nf][1], bfr[nf][2], bfr[nf][3], ad);
            }
#pragma unroll
            for (int ss = 0; ss < 2; ss++) {
                uint32_t a[4][4];
#pragma unroll
                for (int mf = 0; mf < 4; mf++) {
                    uint32_t ad = aAdr0 + mf * 2048 +
                                  (((2 * (s + ss) + lq_) ^ lx) << 4);
                    LDSM4(a[mf][0], a[mf][1], a[mf][2], a[mf][3], ad);
                }
#pragma unroll
                for (int mf = 0; mf < 4; mf++)
#pragma unroll
                    for (int nf = 0; nf < 8; nf++)
                        MMA_TF32(acc[mf][nf], a[mf], bfr[nf][2 * ss], bfr[nf][2 * ss + 1]);
            }
        }
        __syncthreads();
        buf ^= 1;
    }
#undef STAGE_O

#pragma unroll
    for (int mf = 0; mf < 4; mf++) {
        int row = m0 + mw + mf * 16 + (l >> 2);
#pragma unroll
        for (int nf = 0; nf < 8; nf++) {
            int col = n0 + nw + nf * 8 + (l & 3) * 2;
            float2 bb = *(const float2*)&bias[col];
            float2 o0, o1;
            o0.x = acc[mf][nf][0] + bb.x; o0.y = acc[mf][nf][1] + bb.y;
            o1.x = acc[mf][nf][2] + bb.x; o1.y = acc[mf][nf][3] + bb.y;
            *(float2*)&C[(size_t)row * DM + col]       = o0;
            *(float2*)&C[(size_t)(row + 8) * DM + col] = o1;
        }
    }
}

// ============================================================================
// Fused flash attention, 2x2 warp tiling: warp (wm,wn) = 32 queries x 32 keys.
// Halves K/V LDSM traffic per warp. O partials reduced across wn at the end.
// ============================================================================
__global__ __launch_bounds__(128, 2) void flash_attn_tf32(
    const float* __restrict__ Qp, const float* __restrict__ Kp,
    const float* __restrict__ Vt, const unsigned short* __restrict__ bm,
    const float* __restrict__ b_table, float* __restrict__ Ao)
{
    extern __shared__ float smem[];
    const uint32_t sb = s_u32(smem);
    const uint32_t sQ = sb;                       // aliased by P after Q consumed
    const uint32_t sKb[2]  = { sb + 16384, sb + 57344 };
    const uint32_t sVb[2]  = { sb + 32768, sb + 73728 };
    const uint32_t sBMb[2] = { sb + 49152, sb + 90112 };
    const uint32_t bmOff[2] = { 49152, 90112 };
    float* btm  = smem + 98304 / 4;
    float* ssum = smem + 101904 / 4;              // 2 x 64 floats
    float* ostg = smem + 16384 / 4;               // aliases K0/V0 after loop, pitch 68

    const int tid = threadIdx.x;
    const int h = blockIdx.x, b = blockIdx.z;
    const int m0 = blockIdx.y * 64;
    const int l = tid & 31, w = tid >> 5;
    const int wm = w >> 1, wn = w & 1;
    const int mw = wm * 32;                       // query offset of this warp
    const int kq = wn * 32;                       // key offset within the 64-tile
    const int lx = l & 7;

    for (int i = tid; i < VOCAB_B; i += 128) btm[i] = b_table[i * NH + h];

    const float* Qg = Qp + ((size_t)(b * LQ + m0)) * DM + h * DK;
    const float* Kg = Kp + ((size_t)(b * LK)) * DM + h * DK;
    const float* Vg = Vt + ((size_t)(b * DM + h * DK)) * LK;
    const unsigned short* BMg = bm + ((size_t)(b * LQ + m0)) * LK;

#pragma unroll
    for (int i = 0; i < 8; i++) {
        int gi = tid + i * 128;
        int r = gi >> 4, g = gi & 15;
        CP16(sQ + r * 256 + (((g ^ (r & 7)) << 4)), Qg + (size_t)r * DM + g * 4);
    }

#define STAGE_KV(IT, BUF) do {                                                 \
    const float* Ksrc_ = Kg + (size_t)((IT) * 64) * DM;                        \
    const float* Vsrc_ = Vg + (IT) * 64;                                       \
    const unsigned short* Bsrc_ = BMg + (IT) * 64;                             \
    _Pragma("unroll")                                                          \
    for (int i_ = 0; i_ < 8; i_++) {                                           \
        int gi_ = tid + i_ * 128;                                              \
        int r_ = gi_ >> 4, g_ = gi_ & 15;                                      \
        CP16(sKb[BUF] + r_ * 256 + (((g_ ^ (r_ & 7)) << 4)),                   \
             Ksrc_ + (size_t)r_ * DM + g_ * 4);                                \
    }                                                                          \
    _Pragma("unroll")                                                          \
    for (int i_ = 0; i_ < 8; i_++) {                                           \
        int gi_ = tid + i_ * 128;                                              \
        int r_ = gi_ >> 4, g_ = gi_ & 15;                                      \
        CP16(sVb[BUF] + r_ * 256 + (((g_ ^ (r_ & 7)) << 4)),                   \
             Vsrc_ + (size_t)r_ * LK + g_ * 4);                                \
    }                                                                          \
    _Pragma("unroll")                                                          \
    for (int i_ = 0; i_ < 4; i_++) {                                           \
        int gi_ = tid + i_ * 128;                                              \
        int r_ = gi_ >> 3, g_ = gi_ & 7;                                       \
        CP16(sBMb[BUF] + r_ * 128 + (((g_ ^ (r_ & 7)) << 4)),                  \
             Bsrc_ + (size_t)r_ * LK + g_ * 8);                                \
    }                                                                          \
} while (0)

    STAGE_KV(0, 0);
    CPCOMMIT;

    uint32_t aq[2][8][4];
    float oacc[2][8][4];
#pragma unroll
    for (int mi = 0; mi < 2; mi++)
#pragma unroll
        for (int nf = 0; nf < 8; nf++)
#pragma unroll
            for (int r = 0; r < 4; r++) oacc[mi][nf][r] = 0.f;
    float sr[4] = { 0.f, 0.f, 0.f, 0.f };   // [mi*2 + rowhalf]

    int buf = 0;
    for (int it = 0; it < LK / 64; ++it) {
        if (it + 1 < LK / 64) { STAGE_KV(it + 1, buf ^ 1); CPCOMMIT; CPWAIT1; }
        else                  { CPWAIT0; }
        __syncthreads();

        if (it == 0) {
#pragma unroll
            for (int mi = 0; mi < 2; mi++)
#pragma unroll
                for (int kg = 0; kg < 8; kg++) {
                    uint32_t ad = sQ + (mw + mi * 16 + (l & 15)) * 256 +
                                  (((2 * kg + (l >> 4)) ^ lx) << 4);
                    LDSM4(aq[mi][kg][0], aq[mi][kg][1], aq[mi][kg][2], aq[mi][kg][3], ad);
                }
        }

        // ---- S = Q K^T (32q x 32k per warp) ----
        float sval[2][4][4];
#pragma unroll
        for (int mi = 0; mi < 2; mi++)
#pragma unroll
            for (int nfj = 0; nfj < 4; nfj++)
#pragma unroll
                for (int r = 0; r < 4; r++) sval[mi][nfj][r] = 0.f;

#pragma unroll
        for (int s = 0; s < 8; s += 2) {
#pragma unroll
            for (int nfj = 0; nfj < 4; nfj++) {
                uint32_t kb[4];
                uint32_t ad = sKb[buf] + (kq + nfj * 8 + lx) * 256 +
                              (((2 * s + ((l >> 3) & 3)) ^ lx) << 4);
                LDSM4(kb[0], kb[1], kb[2], kb[3], ad);
#pragma unroll
                for (int mi = 0; mi < 2; mi++) {
                    MMA_TF32(sval[mi][nfj], aq[mi][s],     kb[0], kb[1]);
                    MMA_TF32(sval[mi][nfj], aq[mi][s + 1], kb[2], kb[3]);
                }
            }
        }

        // ---- scale + bias gather + mask (select) + unconditional exp ----
        {
            const uint32_t* sm32 = (const uint32_t*)smem;
#pragma unroll
            for (int mi = 0; mi < 2; mi++) {
                const int rl = mw + mi * 16 + (l >> 2);
                const uint32_t rx = (uint32_t)(rl & 7);
#pragma unroll
                for (int nfj = 0; nfj < 4; nfj++) {
                    uint32_t g = (uint32_t)(wn * 4 + nfj);
                    uint32_t o = bmOff[buf] / 4 + rl * 32 + (((g ^ rx) << 2)) + (l & 3);
                    uint32_t e01 = sm32[o];
                    uint32_t e23 = sm32[o + 8 * 32];
                    uint32_t e0 = e01 & 0xffffu, e1 = e01 >> 16;
                    uint32_t e2 = e23 & 0xffffu, e3 = e23 >> 16;
                    float a0 = (e0 & 0x8000u) ? sval[mi][nfj][0] * 0.125f + btm[e0 & 0x3ffu] : -1e30f;
                    float a1 = (e1 & 0x8000u) ? sval[mi][nfj][1] * 0.125f + btm[e1 & 0x3ffu] : -1e30f;
                    float a2 = (e2 & 0x8000u) ? sval[mi][nfj][2] * 0.125f + btm[e2 & 0x3ffu] : -1e30f;
                    float a3 = (e3 & 0x8000u) ? sval[mi][nfj][3] * 0.125f + btm[e3 & 0x3ffu] : -1e30f;
                    sval[mi][nfj][0] = __expf(a0);
                    sval[mi][nfj][1] = __expf(a1);
                    sval[mi][nfj][2] = __expf(a2);
                    sval[mi][nfj][3] = __expf(a3);
                    sr[mi * 2 + 0] += sval[mi][nfj][0] + sval[mi][nfj][1];
                    sr[mi * 2 + 1] += sval[mi][nfj][2] + sval[mi][nfj][3];
                }
            }
        }

        // ---- P -> per-warp 32x32 patch (pitch 128B, aliases Q region) ----
        {
            const uint32_t pb = sQ + w * 4096;
            const int rs0 = l >> 2;
            const uint32_t boff = ((l & 1) << 3);
            __syncwarp();
#pragma unroll
            for (int mi = 0; mi < 2; mi++) {
#pragma unroll
                for (int nfj = 0; nfj < 4; nfj++) {
                    int g = nfj * 2 + ((l & 3) >> 1);
                    uint32_t a0 = pb + (mi * 16 + rs0) * 128 + (((g ^ rs0) << 4)) + boff;
                    float2 p0 = { sval[mi][nfj][0], sval[mi][nfj][1] };
                    float2 p1 = { sval[mi][nfj][2], sval[mi][nfj][3] };
                    *(float2*)(smem + ((a0 - sb) >> 2))        = p0;
                    *(float2*)(smem + ((a0 + 1024 - sb) >> 2)) = p1;
                }
            }
            __syncwarp();
        }

        uint32_t pa[2][4][4];
#pragma unroll
        for (int mi = 0; mi < 2; mi++)
#pragma unroll
            for (int kg = 0; kg < 4; kg++) {
                uint32_t ad = sQ + w * 4096 + (mi * 16 + (l & 15)) * 128 +
                              (((2 * kg + (l >> 4)) ^ lx) << 4);
                LDSM4(pa[mi][kg][0], pa[mi][kg][1], pa[mi][kg][2], pa[mi][kg][3], ad);
                CVT_TF32(pa[mi][kg][0]); CVT_TF32(pa[mi][kg][1]);
                CVT_TF32(pa[mi][kg][2]); CVT_TF32(pa[mi][kg][3]);
            }

        // ---- O += P V (keys restricted to warp's 32-key half) ----
#pragma unroll
        for (int s2 = 0; s2 < 4; s2 += 2) {
#pragma unroll
            for (int nf = 0; nf < 8; nf++) {
                uint32_t bv[4];
                uint32_t ad = sVb[buf] + (nf * 8 + lx) * 256 +
                              (((wn * 8 + 2 * s2 + ((l >> 3) & 3)) ^ lx) << 4);
                LDSM4(bv[0], bv[1], bv[2], bv[3], ad);
#pragma unroll
                for (int mi = 0; mi < 2; mi++) {
                    MMA_TF32(oacc[mi][nf], pa[mi][s2],     bv[0], bv[1]);
                    MMA_TF32(oacc[mi][nf], pa[mi][s2 + 1], bv[2], bv[3]);
                }
            }
        }

        __syncthreads();
        buf ^= 1;
    }
#undef STAGE_KV

    // ---- reduce: quad lanes, then across wn via smem; O partials combined ----
    {
#pragma unroll
        for (int o = 1; o < 4; o <<= 1) {
#pragma unroll
            for (int j = 0; j < 4; j++)
                sr[j] += __shfl_xor_sync(0xffffffffu, sr[j], o);
        }
        if ((l & 3) == 0) {
            ssum[wn * 64 + mw + (l >> 2)]          = sr[0];
            ssum[wn * 64 + mw + (l >> 2) + 8]      = sr[1];
            ssum[wn * 64 + mw + 16 + (l >> 2)]     = sr[2];
            ssum[wn * 64 + mw + 16 + (l >> 2) + 8] = sr[3];
        }
        if (wn == 1) {
#pragma unroll
            for (int mi = 0; mi < 2; mi++) {
                int row = mw + mi * 16 + (l >> 2);
#pragma unroll
                for (int nf = 0; nf < 8; nf++) {
                    int col = nf * 8 + (l & 3) * 2;
                    int bofs = row * 68 + col;
                    ostg[bofs]              = oacc[mi][nf][0];
                    ostg[bofs + 1]          = oacc[mi][nf][1];
                    ostg[bofs + 8 * 68]     = oacc[mi][nf][2];
                    ostg[bofs + 8 * 68 + 1] = oacc[mi][nf][3];
                }
            }
        }
        __syncthreads();
        if (wn == 0) {
#pragma unroll
            for (int mi = 0; mi < 2; mi++) {
                int rl = mw + mi * 16 + (l >> 2);
                float t0 = sr[mi * 2]     + ssum[64 + rl];
                float t1 = sr[mi * 2 + 1] + ssum[64 + rl + 8];
                float i0 = (t0 > 0.f) ? 1.f / t0 : 0.f;
                float i1 = (t1 > 0.f) ? 1.f / t1 : 0.f;
#pragma unroll
                for (int nf = 0; nf < 8; nf++) {
                    int col = nf * 8 + (l & 3) * 2;
                    float2 q0 = *(const float2*)&ostg[rl * 68 + col];
                    float2 q1 = *(const float2*)&ostg[(rl + 8) * 68 + col];
                    float2 o0 = { rtf32((oacc[mi][nf][0] + q0.x) * i0),
                                  rtf32((oacc[mi][nf][1] + q0.y) * i0) };
                    float2 o1 = { rtf32((oacc[mi][nf][2] + q1.x) * i1),
                                  rtf32((oacc[mi][nf][3] + q1.y) * i1) };
                    *(float2*)&Ao[((size_t)(b * LQ + m0 + rl)) * DM + h * DK + col]     = o0;
                    *(float2*)&Ao[((size_t)(b * LQ + m0 + rl + 8)) * DM + h * DK + col] = o1;
                }
            }
        }
    }
}

// ---------------------------------------------------------------------------
extern "C" void kernel_launch(void* const* d_in, const int* in_sizes, int n_in,
                              void* d_out, int out_size)
{
    const float* q       = (const float*)d_in[0];
    const float* k       = (const float*)d_in[1];
    const float* v       = (const float*)d_in[2];
    const int*   b_idx   = (const int*)  d_in[3];
    const int*   mask    = (const int*)  d_in[4];
    const float* Wq      = (const float*)d_in[5];
    const float* bq      = (const float*)d_in[6];
    const float* Wk      = (const float*)d_in[7];
    const float* bk      = (const float*)d_in[8];
    const float* Wv      = (const float*)d_in[9];
    const float* bv      = (const float*)d_in[10];
    const float* Wo      = (const float*)d_in[11];
    const float* bo      = (const float*)d_in[12];
    const float* b_table = (const float*)d_in[13];
    float* out = (float*)d_out;

    void *Qp_, *Kp_, *Vt_, *Ao_, *bm_, *Wr_;
    cudaGetSymbolAddress(&Qp_, g_Qp);
    cudaGetSymbolAddress(&Kp_, g_Kp);
    cudaGetSymbolAddress(&Vt_, g_Vt);
    cudaGetSymbolAddress(&Ao_, g_Ao);
    cudaGetSymbolAddress(&bm_, g_bm);
    cudaGetSymbolAddress(&Wr_, g_Wr);
    float* Qp = (float*)Qp_;
    float* Kp = (float*)Kp_;
    float* Vt = (float*)Vt_;
    float* Ao = (float*)Ao_;
    float* Wr = (float*)Wr_;
    unsigned short* bm = (unsigned short*)bm_;

    static int attr_set = 0;
    if (!attr_set) {
        cudaFuncSetAttribute((const void*)proj_qkv_tf32,   cudaFuncAttributeMaxDynamicSharedMemorySize, 69632);
        cudaFuncSetAttribute((const void*)gemm_out_tf32,   cudaFuncAttributeMaxDynamicSharedMemorySize, 65536);
        cudaFuncSetAttribute((const void*)flash_attn_tf32, cudaFuncAttributeMaxDynamicSharedMemorySize, 102416);
        attr_set = 1;
    }

    // prep: pack bias/mask + round all weights
    const int NB4 = BSZ * LQ * LK / 4;
    const int NW4 = DM * DM / 4;
    pack_bm_kernel<<<1024, 256>>>((const int4*)b_idx, (const int4*)mask, (ushort4*)bm, NB4);
    round_w4_kernel<<<dim3(64, 4), 256>>>((const float4*)Wq, (const float4*)Wk,
                                          (const float4*)Wv, (const float4*)Wo,
                                          (float4*)Wr, NW4);

    // fused Q/K/V projections
    proj_qkv_tf32<<<dim3(DM / 128, 144), 128, 69632>>>(
        q, k, v, Wr, bq, bk, bv, Qp, Kp, Vt);

    // fused attention (2x2 warp-tiled)
    flash_attn_tf32<<<dim3(NH, LQ / 64, BSZ), 128, 102416>>>(
        Qp, Kp, Vt, bm, b_table, Ao);

    // output projection
    gemm_out_tf32<<<dim3(DM / 128, (BSZ * LQ) / 128), 128, 65536>>>(
        Ao, Wr + 3 * DM * DM, bo, out);
}

// round 17
// speedup vs baseline: 1.0173x; 1.0173x over previous
#include <cuda_runtime.h>
#include <cstdint>

#define BSZ 4
#define LQ  512
#define LK  2048
#define DM  1024
#define NH  16
#define DK  64
#define VOCAB_B 900

// ---------------- scratch (static device memory; no runtime alloc) ----------
__device__ float g_Qp[BSZ * LQ * DM];
__device__ float g_Kp[BSZ * LK * DM];
__device__ float g_Vt[BSZ * DM * LK];                  // V projected+transposed
__device__ float g_Ao[BSZ * LQ * DM];
__device__ float g_Wr[4 * DM * DM];                    // tf32-rounded weights
__device__ unsigned short g_bm[BSZ * LQ * LK];         // packed b_idx|mask<<15

// ---------------- PTX helpers ----------------------------------------------
__device__ __forceinline__ uint32_t s_u32(const void* p) {
    uint32_t a;
    asm("{.reg .u64 t; cvta.to.shared.u64 t, %1; cvt.u32.u64 %0, t;}"
        : "=r"(a) : "l"(p));
    return a;
}

__device__ __forceinline__ float rtf32(float x) {
    uint32_t u = __float_as_uint(x);
    asm("cvt.rna.tf32.f32 %0,%0;" : "+r"(u));
    return __uint_as_float(u);
}

__device__ __forceinline__ float ex2f(float x) {
    float y;
    asm("ex2.approx.f32 %0,%1;" : "=f"(y) : "f"(x));
    return y;
}

#define LDSM4(R0,R1,R2,R3,ADDR) \
    asm volatile("ldmatrix.sync.aligned.m8n8.x4.shared.b16 {%0,%1,%2,%3},[%4];" \
        : "=r"(R0),"=r"(R1),"=r"(R2),"=r"(R3) : "r"(ADDR))

#define CVT_TF32(T) asm volatile("cvt.rna.tf32.f32 %0,%0;" : "+r"(T))

#define MMA_TF32(D,A,B0,B1) \
    asm volatile("mma.sync.aligned.m16n8k8.row.col.f32.tf32.tf32.f32 " \
        "{%0,%1,%2,%3},{%4,%5,%6,%7},{%8,%9},{%0,%1,%2,%3};" \
        : "+f"(D[0]),"+f"(D[1]),"+f"(D[2]),"+f"(D[3]) \
        : "r"(A[0]),"r"(A[1]),"r"(A[2]),"r"(A[3]),"r"(B0),"r"(B1))

#define CP16(DST,SRC) \
    asm volatile("cp.async.cg.shared.global [%0],[%1],16;" :: "r"(DST),"l"(SRC))
#define CPCOMMIT  asm volatile("cp.async.commit_group;")
#define CPWAIT0   asm volatile("cp.async.wait_group 0;")
#define CPWAIT1   asm volatile("cp.async.wait_group 1;")

// ============================================================================
// round all 4 weight matrices in ONE launch
// ============================================================================
__global__ __launch_bounds__(256) void round_w4_kernel(
    const float4* __restrict__ w0, const float4* __restrict__ w1,
    const float4* __restrict__ w2, const float4* __restrict__ w3,
    float4* __restrict__ out, int n4)
{
    const float4* src = (blockIdx.y == 0) ? w0 : (blockIdx.y == 1) ? w1 :
                        (blockIdx.y == 2) ? w2 : w3;
    float4* dst = out + (size_t)blockIdx.y * n4;
    const int s = gridDim.x * 256;
    for (int i = blockIdx.x * 256 + threadIdx.x; i < n4; i += s) {
        float4 v = src[i];
        v.x = rtf32(v.x); v.y = rtf32(v.y);
        v.z = rtf32(v.z); v.w = rtf32(v.w);
        dst[i] = v;
    }
}

// ============================================================================
// pack b_idx + mask -> uint16 (idx | mask<<15), 4x ILP grid-strided
// ============================================================================
__device__ __forceinline__ ushort4 pack4(int4 ix, int4 mk) {
    ushort4 o;
    o.x = (unsigned short)(ix.x | (mk.x << 15));
    o.y = (unsigned short)(ix.y | (mk.y << 15));
    o.z = (unsigned short)(ix.z | (mk.z << 15));
    o.w = (unsigned short)(ix.w | (mk.w << 15));
    return o;
}
__global__ __launch_bounds__(256) void pack_bm_kernel(
    const int4* __restrict__ b_idx, const int4* __restrict__ mask,
    ushort4* __restrict__ bm, int n4)
{
    const int s = gridDim.x * 256;
    int i = blockIdx.x * 256 + threadIdx.x;
    if (i + 3 * s < n4) {
        int4 a0 = b_idx[i],         a1 = b_idx[i + s],
             a2 = b_idx[i + 2 * s], a3 = b_idx[i + 3 * s];
        int4 m0 = mask[i],          m1 = mask[i + s],
             m2 = mask[i + 2 * s],  m3 = mask[i + 3 * s];
        bm[i]         = pack4(a0, m0);
        bm[i + s]     = pack4(a1, m1);
        bm[i + 2 * s] = pack4(a2, m2);
        bm[i + 3 * s] = pack4(a3, m3);
    } else {
        for (; i < n4; i += s) bm[i] = pack4(b_idx[i], mask[i]);
    }
}

// ============================================================================
// FUSED Q/K/V projection (round-15 proven)
// ============================================================================
__global__ __launch_bounds__(128, 2) void proj_qkv_tf32(
    const float* __restrict__ q, const float* __restrict__ k,
    const float* __restrict__ v, const float* __restrict__ Wr,
    const float* __restrict__ bq, const float* __restrict__ bk,
    const float* __restrict__ bv,
    float* __restrict__ Qp, float* __restrict__ Kp, float* __restrict__ Vt)
{
    extern __shared__ float smem[];
    const uint32_t sbase = s_u32(smem);
    const int tid = threadIdx.x;
    const int y = blockIdx.y;

    const float* A;  const float* B;  const float* bias;  float* C;
    int m0;  bool transv;
    if (y < 16)      { A = q; B = Wr;              bias = bq; C = Qp; m0 = y * 128;        transv = false; }
    else if (y < 80) { A = k; B = Wr + DM * DM;    bias = bk; C = Kp; m0 = (y - 16) * 128; transv = false; }
    else             { A = v; B = Wr + 2 * DM * DM; bias = bv; C = Vt; m0 = (y - 80) * 128; transv = true; }

    const int n0 = blockIdx.x * 128;
    const int l  = tid & 31, w = tid >> 5;
    const int mw = (w >> 1) * 64, nw = (w & 1) * 64;
    const int lrow = l & 15, lq_ = l >> 4, lx = l & 7;

    float acc[4][8][4];
#pragma unroll
    for (int i = 0; i < 4; i++)
#pragma unroll
        for (int j = 0; j < 8; j++)
#pragma unroll
            for (int r = 0; r < 4; r++) acc[i][j][r] = 0.f;

#define STAGE_P(IT, BUF) do {                                                  \
    uint32_t sA_ = sbase + (BUF) * 32768;                                      \
    uint32_t sB_ = sA_ + 16384;                                                \
    const float* Ag_ = A + (size_t)(m0) * DM + (IT) * 32;                      \
    const float* Bg_ = B + (size_t)(n0) * DM + (IT) * 32;                      \
    _Pragma("unroll")                                                          \
    for (int i_ = 0; i_ < 8; i_++) {                                           \
        int gi_ = tid + i_ * 128;                                              \
        int r_ = gi_ >> 3, g_ = gi_ & 7;                                       \
        CP16(sA_ + r_ * 128 + (((g_ ^ (r_ & 7)) << 4)),                        \
             Ag_ + (size_t)r_ * DM + g_ * 4);                                  \
    }                                                                          \
    _Pragma("unroll")                                                          \
    for (int i_ = 0; i_ < 8; i_++) {                                           \
        int gi_ = tid + i_ * 128;                                              \
        int r_ = gi_ >> 3, g_ = gi_ & 7;                                       \
        CP16(sB_ + r_ * 128 + (((g_ ^ (r_ & 7)) << 4)),                        \
             Bg_ + (size_t)r_ * DM + g_ * 4);                                  \
    }                                                                          \
} while (0)

    STAGE_P(0, 0);
    CPCOMMIT;

    int buf = 0;
    for (int it = 0; it < DM / 32; ++it) {
        if (it + 1 < DM / 32) { STAGE_P(it + 1, buf ^ 1); CPCOMMIT; CPWAIT1; }
        else                  { CPWAIT0; }
        __syncthreads();

        const uint32_t sA = sbase + buf * 32768;
        const uint32_t sB = sA + 16384;
        const uint32_t aAdr0 = sA + (mw + lrow) * 128;
        const uint32_t bAdr0 = sB + (nw + (l & 7)) * 128;

#pragma unroll
        for (int s = 0; s < 4; s += 2) {
            uint32_t bfr[8][4];
#pragma unroll
            for (int nf = 0; nf < 8; nf++) {
                uint32_t ad = bAdr0 + nf * 1024 +
                              (((2 * s + ((l >> 3) & 3)) ^ lx) << 4);
                LDSM4(bfr[nf][0], bfr[nf][1], bfr[nf][2], bfr[nf][3], ad);
            }
#pragma unroll
            for (int ss = 0; ss < 2; ss++) {
                uint32_t a[4][4];
#pragma unroll
                for (int mf = 0; mf < 4; mf++) {
                    uint32_t ad = aAdr0 + mf * 2048 +
                                  (((2 * (s + ss) + lq_) ^ lx) << 4);
                    LDSM4(a[mf][0], a[mf][1], a[mf][2], a[mf][3], ad);
                    CVT_TF32(a[mf][0]); CVT_TF32(a[mf][1]);
                    CVT_TF32(a[mf][2]); CVT_TF32(a[mf][3]);
                }
#pragma unroll
                for (int mf = 0; mf < 4; mf++)
#pragma unroll
                    for (int nf = 0; nf < 8; nf++)
                        MMA_TF32(acc[mf][nf], a[mf], bfr[nf][2 * ss], bfr[nf][2 * ss + 1]);
            }
        }
        __syncthreads();
        buf ^= 1;
    }
#undef STAGE_P

    if (transv) {
        __syncthreads();
#pragma unroll
        for (int mf = 0; mf < 4; mf++) {
            int mloc = mw + mf * 16 + (l >> 2);
#pragma unroll
            for (int nf = 0; nf < 8; nf++) {
                int nloc = nw + nf * 8 + (l & 3) * 2;
                float2 bb = *(const float2*)&bias[n0 + nloc];
                smem[(nloc)     * 132 + mloc]     = rtf32(acc[mf][nf][0] + bb.x);
                smem[(nloc + 1) * 132 + mloc]     = rtf32(acc[mf][nf][1] + bb.y);
                smem[(nloc)     * 132 + mloc + 8] = rtf32(acc[mf][nf][2] + bb.x);
                smem[(nloc + 1) * 132 + mloc + 8] = rtf32(acc[mf][nf][3] + bb.y);
            }
        }
        __syncthreads();
        const int bb_ = m0 / LK;
        const int kb_ = m0 % LK;
#pragma unroll
        for (int i = 0; i < 32; i++) {
            int n = w * 32 + i;
            float4 vv = *(const float4*)&smem[n * 132 + 4 * l];
            *(float4*)&C[((size_t)(bb_ * DM + n0 + n)) * LK + kb_ + 4 * l] = vv;
        }
    } else {
#pragma unroll
        for (int mf = 0; mf < 4; mf++) {
            int row = m0 + mw + mf * 16 + (l >> 2);
#pragma unroll
            for (int nf = 0; nf < 8; nf++) {
                int col = n0 + nw + nf * 8 + (l & 3) * 2;
                float2 bb = *(const float2*)&bias[col];
                float2 o0, o1;
                o0.x = rtf32(acc[mf][nf][0] + bb.x);
                o0.y = rtf32(acc[mf][nf][1] + bb.y);
                o1.x = rtf32(acc[mf][nf][2] + bb.x);
                o1.y = rtf32(acc[mf][nf][3] + bb.y);
                *(float2*)&C[(size_t)row * DM + col]       = o0;
                *(float2*)&C[(size_t)(row + 8) * DM + col] = o1;
            }
        }
    }
}

// ============================================================================
// Output projection (round-15 proven)
// ============================================================================
__global__ __launch_bounds__(128, 2) void gemm_out_tf32(
    const float* __restrict__ A, const float* __restrict__ B,
    const float* __restrict__ bias, float* __restrict__ C)
{
    extern __shared__ float smem[];
    const uint32_t sbase = s_u32(smem);
    const int tid = threadIdx.x;
    const int m0 = blockIdx.y * 128, n0 = blockIdx.x * 128;
    const int l  = tid & 31, w = tid >> 5;
    const int mw = (w >> 1) * 64, nw = (w & 1) * 64;
    const int lrow = l & 15, lq_ = l >> 4, lx = l & 7;

    float acc[4][8][4];
#pragma unroll
    for (int i = 0; i < 4; i++)
#pragma unroll
        for (int j = 0; j < 8; j++)
#pragma unroll
            for (int r = 0; r < 4; r++) acc[i][j][r] = 0.f;

#define STAGE_O(IT, BUF) do {                                                  \
    uint32_t sA_ = sbase + (BUF) * 32768;                                      \
    uint32_t sB_ = sA_ + 16384;                                                \
    const float* Ag_ = A + (size_t)(m0) * DM + (IT) * 32;                      \
    const float* Bg_ = B + (size_t)(n0) * DM + (IT) * 32;                      \
    _Pragma("unroll")                                                          \
    for (int i_ = 0; i_ < 8; i_++) {                                           \
        int gi_ = tid + i_ * 128;                                              \
        int r_ = gi_ >> 3, g_ = gi_ & 7;                                       \
        CP16(sA_ + r_ * 128 + (((g_ ^ (r_ & 7)) << 4)),                        \
             Ag_ + (size_t)r_ * DM + g_ * 4);                                  \
    }                                                                          \
    _Pragma("unroll")                                                          \
    for (int i_ = 0; i_ < 8; i_++) {                                           \
        int gi_ = tid + i_ * 128;                                              \
        int r_ = gi_ >> 3, g_ = gi_ & 7;                                       \
        CP16(sB_ + r_ * 128 + (((g_ ^ (r_ & 7)) << 4)),                        \
             Bg_ + (size_t)r_ * DM + g_ * 4);                                  \
    }                                                                          \
} while (0)

    STAGE_O(0, 0);
    CPCOMMIT;

    int buf = 0;
    for (int it = 0; it < DM / 32; ++it) {
        if (it + 1 < DM / 32) { STAGE_O(it + 1, buf ^ 1); CPCOMMIT; CPWAIT1; }
        else                  { CPWAIT0; }
        __syncthreads();

        const uint32_t sA = sbase + buf * 32768;
        const uint32_t sB = sA + 16384;
        const uint32_t aAdr0 = sA + (mw + lrow) * 128;
        const uint32_t bAdr0 = sB + (nw + (l & 7)) * 128;

#pragma unroll
        for (int s = 0; s < 4; s += 2) {
            uint32_t bfr[8][4];
#pragma unroll
            for (int nf = 0; nf < 8; nf++) {
                uint32_t ad = bAdr0 + nf * 1024 +
                              (((2 * s + ((l >> 3) & 3)) ^ lx) << 4);
                LDSM4(bfr[nf][0], bfr[nf][1], bfr[nf][2], bfr[nf][3], ad);
            }
#pragma unroll
            for (int ss = 0; ss < 2; ss++) {
                uint32_t a[4][4];
#pragma unroll
                for (int mf = 0; mf < 4; mf++) {
                    uint32_t ad = aAdr0 + mf * 2048 +
                                  (((2 * (s + ss) + lq_) ^ lx) << 4);
                    LDSM4(a[mf][0], a[mf][1], a[mf][2], a[mf][3], ad);
                }
#pragma unroll
                for (int mf = 0; mf < 4; mf++)
#pragma unroll
                    for (int nf = 0; nf < 8; nf++)
                        MMA_TF32(acc[mf][nf], a[mf], bfr[nf][2 * ss], bfr[nf][2 * ss + 1]);
            }
        }
        __syncthreads();
        buf ^= 1;
    }
#undef STAGE_O

#pragma unroll
    for (int mf = 0; mf < 4; mf++) {
        int row = m0 + mw + mf * 16 + (l >> 2);
#pragma unroll
        for (int nf = 0; nf < 8; nf++) {
            int col = n0 + nw + nf * 8 + (l & 3) * 2;
            float2 bb = *(const float2*)&bias[col];
            float2 o0, o1;
            o0.x = acc[mf][nf][0] + bb.x; o0.y = acc[mf][nf][1] + bb.y;
            o1.x = acc[mf][nf][2] + bb.x; o1.y = acc[mf][nf][3] + bb.y;
            *(float2*)&C[(size_t)row * DM + col]       = o0;
            *(float2*)&C[(size_t)(row + 8) * DM + col] = o1;
        }
    }
}

// ============================================================================
// Fused flash attention (round-15 proven shape). CTA: 64 queries, 4 warps,
// 2 CTAs/SM. No-max softmax, branchless; exp via single ex2.approx with
// log2e folded into the scale and the staged bias column.
// ============================================================================
__global__ __launch_bounds__(128, 2) void flash_attn_tf32(
    const float* __restrict__ Qp, const float* __restrict__ Kp,
    const float* __restrict__ Vt, const unsigned short* __restrict__ bm,
    const float* __restrict__ b_table, float* __restrict__ Ao)
{
    extern __shared__ float smem[];
    const uint32_t sb = s_u32(smem);
    const uint32_t sQ = sb;                       // aliased by P after Q consumed
    const uint32_t sKb[2]  = { sb + 16384, sb + 57344 };
    const uint32_t sVb[2]  = { sb + 32768, sb + 73728 };
    const uint32_t sBMb[2] = { sb + 49152, sb + 90112 };
    const uint32_t bmOff[2] = { 49152, 90112 };
    float* btm = smem + 98304 / 4;

    const float L2E  = 1.4426950408889634f;
    const float SC12 = 0.125f * L2E;              // (1/8)*log2(e)

    const int tid = threadIdx.x;
    const int h = blockIdx.x, b = blockIdx.z;
    const int m0 = blockIdx.y * 64;
    const int l = tid & 31, w = tid >> 5;
    const int mw = w * 16;
    const int lx = l & 7;

    for (int i = tid; i < VOCAB_B; i += 128) btm[i] = b_table[i * NH + h] * L2E;

    const float* Qg = Qp + ((size_t)(b * LQ + m0)) * DM + h * DK;
    const float* Kg = Kp + ((size_t)(b * LK)) * DM + h * DK;
    const float* Vg = Vt + ((size_t)(b * DM + h * DK)) * LK;
    const unsigned short* BMg = bm + ((size_t)(b * LQ + m0)) * LK;

#pragma unroll
    for (int i = 0; i < 8; i++) {
        int gi = tid + i * 128;
        int r = gi >> 4, g = gi & 15;
        CP16(sQ + r * 256 + (((g ^ (r & 7)) << 4)), Qg + (size_t)r * DM + g * 4);
    }

#define STAGE_KV(IT, BUF) do {                                                 \
    const float* Ksrc_ = Kg + (size_t)((IT) * 64) * DM;                        \
    const float* Vsrc_ = Vg + (IT) * 64;                                       \
    const unsigned short* Bsrc_ = BMg + (IT) * 64;                             \
    _Pragma("unroll")                                                          \
    for (int i_ = 0; i_ < 8; i_++) {                                           \
        int gi_ = tid + i_ * 128;                                              \
        int r_ = gi_ >> 4, g_ = gi_ & 15;                                      \
        CP16(sKb[BUF] + r_ * 256 + (((g_ ^ (r_ & 7)) << 4)),                   \
             Ksrc_ + (size_t)r_ * DM + g_ * 4);                                \
    }                                                                          \
    _Pragma("unroll")                                                          \
    for (int i_ = 0; i_ < 8; i_++) {                                           \
        int gi_ = tid + i_ * 128;                                              \
        int r_ = gi_ >> 4, g_ = gi_ & 15;                                      \
        CP16(sVb[BUF] + r_ * 256 + (((g_ ^ (r_ & 7)) << 4)),                   \
             Vsrc_ + (size_t)r_ * LK + g_ * 4);                                \
    }                                                                          \
    _Pragma("unroll")                                                          \
    for (int i_ = 0; i_ < 4; i_++) {                                           \
        int gi_ = tid + i_ * 128;                                              \
        int r_ = gi_ >> 3, g_ = gi_ & 7;                                       \
        CP16(sBMb[BUF] + r_ * 128 + (((g_ ^ (r_ & 7)) << 4)),                  \
             Bsrc_ + (size_t)r_ * LK + g_ * 8);                                \
    }                                                                          \
} while (0)

    STAGE_KV(0, 0);
    CPCOMMIT;

    uint32_t aq[8][4];
    float oacc[8][4];
#pragma unroll
    for (int nf = 0; nf < 8; nf++)
#pragma unroll
        for (int r = 0; r < 4; r++) oacc[nf][r] = 0.f;
    float sr0 = 0.f, sr1 = 0.f;

    const int lr = mw + (l >> 2);
    const uint32_t lrx = (uint32_t)(lr & 7);

    int buf = 0;
    for (int it = 0; it < LK / 64; ++it) {
        if (it + 1 < LK / 64) { STAGE_KV(it + 1, buf ^ 1); CPCOMMIT; CPWAIT1; }
        else                  { CPWAIT0; }
        __syncthreads();

        if (it == 0) {
#pragma unroll
            for (int kg = 0; kg < 8; kg++) {
                uint32_t ad = sQ + (mw + (l & 15)) * 256 +
                              (((2 * kg + (l >> 4)) ^ lx) << 4);
                LDSM4(aq[kg][0], aq[kg][1], aq[kg][2], aq[kg][3], ad);
            }
        }

        // ---- S = Q K^T ----
        float sval[8][4];
#pragma unroll
        for (int nf = 0; nf < 8; nf++)
#pragma unroll
            for (int r = 0; r < 4; r++) sval[nf][r] = 0.f;

#pragma unroll
        for (int s = 0; s < 8; s += 2) {
#pragma unroll
            for (int nf = 0; nf < 8; nf++) {
                uint32_t kb[4];
                uint32_t ad = sKb[buf] + (nf * 8 + lx) * 256 +
                              (((2 * s + ((l >> 3) & 3)) ^ lx) << 4);
                LDSM4(kb[0], kb[1], kb[2], kb[3], ad);
                MMA_TF32(sval[nf], aq[s],     kb[0], kb[1]);
                MMA_TF32(sval[nf], aq[s + 1], kb[2], kb[3]);
            }
        }

        // ---- scale + bias gather + mask (SELECT) then single ex2 ----
        {
            const uint32_t base = bmOff[buf] / 4 + lr * 32 + (l & 3);
            const uint32_t* sm32 = (const uint32_t*)smem;
#pragma unroll
            for (int nf = 0; nf < 8; nf++) {
                uint32_t o = base + (((uint32_t)nf ^ lrx) << 2);
                uint32_t e01 = sm32[o];
                uint32_t e23 = sm32[o + 8 * 32];
                uint32_t e0 = e01 & 0xffffu, e1 = e01 >> 16;
                uint32_t e2 = e23 & 0xffffu, e3 = e23 >> 16;
                float a0 = (e0 & 0x8000u) ? sval[nf][0] * SC12 + btm[e0 & 0x3ffu] : -1e30f;
                float a1 = (e1 & 0x8000u) ? sval[nf][1] * SC12 + btm[e1 & 0x3ffu] : -1e30f;
                float a2 = (e2 & 0x8000u) ? sval[nf][2] * SC12 + btm[e2 & 0x3ffu] : -1e30f;
                float a3 = (e3 & 0x8000u) ? sval[nf][3] * SC12 + btm[e3 & 0x3ffu] : -1e30f;
                sval[nf][0] = ex2f(a0);
                sval[nf][1] = ex2f(a1);
                sval[nf][2] = ex2f(a2);
                sval[nf][3] = ex2f(a3);
                sr0 += sval[nf][0] + sval[nf][1];
                sr1 += sval[nf][2] + sval[nf][3];
            }
        }

        // ---- P -> per-warp patch (aliases this warp's Q rows) ----
        {
            const uint32_t pb = sQ + w * 4096;
            const int rs0 = l >> 2;
            const uint32_t boff = ((l & 1) << 3);
            __syncwarp();
#pragma unroll
            for (int nf = 0; nf < 8; nf++) {
                int g = nf * 2 + ((l & 3) >> 1);
                uint32_t a0 = pb + rs0 * 256 + (((g ^ rs0) << 4)) + boff;
                uint32_t a1 = pb + (rs0 + 8) * 256 + (((g ^ rs0) << 4)) + boff;
                float2 p0 = { sval[nf][0], sval[nf][1] };
                float2 p1 = { sval[nf][2], sval[nf][3] };
                *(float2*)(smem + ((a0 - sb) >> 2)) = p0;
                *(float2*)(smem + ((a1 - sb) >> 2)) = p1;
            }
            __syncwarp();
        }

        uint32_t pa[8][4];
#pragma unroll
        for (int kg = 0; kg < 8; kg++) {
            uint32_t ad = sQ + w * 4096 + (l & 15) * 256 +
                          (((2 * kg + (l >> 4)) ^ lx) << 4);
            LDSM4(pa[kg][0], pa[kg][1], pa[kg][2], pa[kg][3], ad);
            CVT_TF32(pa[kg][0]); CVT_TF32(pa[kg][1]);
            CVT_TF32(pa[kg][2]); CVT_TF32(pa[kg][3]);
        }

        // ---- O += P V ----
#pragma unroll
        for (int s = 0; s < 8; s += 2) {
#pragma unroll
            for (int nf = 0; nf < 8; nf++) {
                uint32_t bv[4];
                uint32_t ad = sVb[buf] + (nf * 8 + lx) * 256 +
                              (((2 * s + ((l >> 3) & 3)) ^ lx) << 4);
                LDSM4(bv[0], bv[1], bv[2], bv[3], ad);
                MMA_TF32(oacc[nf], pa[s],     bv[0], bv[1]);
                MMA_TF32(oacc[nf], pa[s + 1], bv[2], bv[3]);
            }
        }

        __syncthreads();
        buf ^= 1;
    }
#undef STAGE_KV

    // ---- reduce sums across the 4 lanes sharing each row, write O ----
    {
#pragma unroll
        for (int o = 1; o < 4; o <<= 1) {
            sr0 += __shfl_xor_sync(0xffffffffu, sr0, o);
            sr1 += __shfl_xor_sync(0xffffffffu, sr1, o);
        }
        const float i0 = (sr0 > 0.f) ? 1.f / sr0 : 0.f;
        const float i1 = (sr1 > 0.f) ? 1.f / sr1 : 0.f;
        const int r0 = m0 + mw + (l >> 2);
#pragma unroll
        for (int nf = 0; nf < 8; nf++) {
            int col = h * DK + nf * 8 + (l & 3) * 2;
            float2 o0 = { rtf32(oacc[nf][0] * i0), rtf32(oacc[nf][1] * i0) };
            float2 o1 = { rtf32(oacc[nf][2] * i1), rtf32(oacc[nf][3] * i1) };
            *(float2*)&Ao[((size_t)(b * LQ + r0)) * DM + col]     = o0;
            *(float2*)&Ao[((size_t)(b * LQ + r0 + 8)) * DM + col] = o1;
        }
    }
}

// ---------------------------------------------------------------------------
extern "C" void kernel_launch(void* const* d_in, const int* in_sizes, int n_in,
                              void* d_out, int out_size)
{
    const float* q       = (const float*)d_in[0];
    const float* k       = (const float*)d_in[1];
    const float* v       = (const float*)d_in[2];
    const int*   b_idx   = (const int*)  d_in[3];
    const int*   mask    = (const int*)  d_in[4];
    const float* Wq      = (const float*)d_in[5];
    const float* bq      = (const float*)d_in[6];
    const float* Wk      = (const float*)d_in[7];
    const float* bk      = (const float*)d_in[8];
    const float* Wv      = (const float*)d_in[9];
    const float* bv      = (const float*)d_in[10];
    const float* Wo      = (const float*)d_in[11];
    const float* bo      = (const float*)d_in[12];
    const float* b_table = (const float*)d_in[13];
    float* out = (float*)d_out;

    void *Qp_, *Kp_, *Vt_, *Ao_, *bm_, *Wr_;
    cudaGetSymbolAddress(&Qp_, g_Qp);
    cudaGetSymbolAddress(&Kp_, g_Kp);
    cudaGetSymbolAddress(&Vt_, g_Vt);
    cudaGetSymbolAddress(&Ao_, g_Ao);
    cudaGetSymbolAddress(&bm_, g_bm);
    cudaGetSymbolAddress(&Wr_, g_Wr);
    float* Qp = (float*)Qp_;
    float* Kp = (float*)Kp_;
    float* Vt = (float*)Vt_;
    float* Ao = (float*)Ao_;
    float* Wr = (float*)Wr_;
    unsigned short* bm = (unsigned short*)bm_;

    static int attr_set = 0;
    if (!attr_set) {
        cudaFuncSetAttribute((const void*)proj_qkv_tf32,   cudaFuncAttributeMaxDynamicSharedMemorySize, 69632);
        cudaFuncSetAttribute((const void*)gemm_out_tf32,   cudaFuncAttributeMaxDynamicSharedMemorySize, 65536);
        cudaFuncSetAttribute((const void*)flash_attn_tf32, cudaFuncAttributeMaxDynamicSharedMemorySize, 101904);
        attr_set = 1;
    }

    // prep: pack bias/mask + round all weights
    const int NB4 = BSZ * LQ * LK / 4;
    const int NW4 = DM * DM / 4;
    pack_bm_kernel<<<1024, 256>>>((const int4*)b_idx, (const int4*)mask, (ushort4*)bm, NB4);
    round_w4_kernel<<<dim3(64, 4), 256>>>((const float4*)Wq, (const float4*)Wk,
                                          (const float4*)Wv, (const float4*)Wo,
                                          (float4*)Wr, NW4);

    // fused Q/K/V projections
    proj_qkv_tf32<<<dim3(DM / 128, 144), 128, 69632>>>(
        q, k, v, Wr, bq, bk, bv, Qp, Kp, Vt);

    // fused attention
    flash_attn_tf32<<<dim3(NH, LQ / 64, BSZ), 128, 101904>>>(
        Qp, Kp, Vt, bm, b_table, Ao);

    // output projection
    gemm_out_tf32<<<dim3(DM / 128, (BSZ * LQ) / 128), 128, 65536>>>(
        Ao, Wr + 3 * DM * DM, bo, out);
}